// round 7
// baseline (speedup 1.0000x reference)
#include <cuda_runtime.h>

// out[b, s, d] = in[b, s, d] + PE[s, d]
// PE[s, 2i]   = sin(s / 10000^(2i/1024)),  PE[s, 2i+1] = cos(...)
//
// B=8, S=4096, D=1024, fp32 — 268 MB per launch, DRAM-bound (~73% spec).
// R7: persistent grid. 4096 CTAs at 8 CTAs/SM = 3.46 waves -> 3 wave
// transitions (~2360 cyc each) + a ragged 46% tail wave. Launch exactly
// 148*8 = 1184 CTAs, each grid-striding over sequence positions: one wave,
// no transitions, smooth drain. Also: issue the batch-0 load before the
// sincos chain so MUFU latency overlaps the first DRAM access.
// (Reverted R6's 256-bit ops: fewer in-flight requests regressed to 41us.
//  L2 policy hints: proven inert in R3-R5. float4 + 256-thr rows is best.)

#define SEQ_LEN 4096
#define D_MODEL 1024
#define BATCH   8
#define THREADS 256          // 256 threads * float4 = 1024 floats = one PE row
#define NUM_SMS 148
#define CTAS_PER_SM 8
#define GRID (NUM_SMS * CTAS_PER_SM)   // 1184 — one full wave

__global__ void __launch_bounds__(THREADS, CTAS_PER_SM)
pe_add_kernel(const float4* __restrict__ in, float4* __restrict__ out) {
    const int t = threadIdx.x;                       // float4 index in row
    const int row_f4       = D_MODEL / 4;            // 256
    const int batch_stride = SEQ_LEN * row_f4;       // 1,048,576 float4s

    const float LOG2_10000 = 13.287712379549449f;
    // Per-thread frequency constants (position-independent): compute once.
    const float inv_d0 = 1.0f / exp2f(((float)(4 * t)     * (1.0f / 1024.0f)) * LOG2_10000);
    const float inv_d1 = 1.0f / exp2f(((float)(4 * t + 2) * (1.0f / 1024.0f)) * LOG2_10000);

    for (int pos = blockIdx.x; pos < SEQ_LEN; pos += GRID) {
        int idx = pos * row_f4 + t;

        // Kick off the first load immediately; sincos overlaps its latency.
        float4 cur = __ldg(in + idx);

        const float fpos = (float)pos;
        float s0, c0, s1, c1;
        sincosf(fpos * inv_d0, &s0, &c0);   // accurate: angles reach ~4095 rad
        sincosf(fpos * inv_d1, &s1, &c1);

#pragma unroll
        for (int b = 0; b < BATCH; ++b) {
            int next_idx = idx + batch_stride;
            float4 nxt;
            if (b < BATCH - 1) nxt = __ldg(in + next_idx);
            float4 v = cur;
            v.x += s0;
            v.y += c0;
            v.z += s1;
            v.w += c1;
            out[idx] = v;
            cur = nxt;
            idx = next_idx;
        }
    }
}

extern "C" void kernel_launch(void* const* d_in, const int* in_sizes, int n_in,
                              void* d_out, int out_size) {
    const float4* in  = (const float4*)d_in[0];
    float4*       out = (float4*)d_out;
    pe_add_kernel<<<GRID, THREADS>>>(in, out);
}

// round 8
// speedup vs baseline: 1.1800x; 1.1800x over previous
#include <cuda_runtime.h>

// out[b, s, d] = in[b, s, d] + PE[s, d]
// PE[s, 2i]   = sin(s / 10000^(2i/1024)),  PE[s, 2i+1] = cos(...)
//
// B=8, S=4096, D=1024, fp32 — 268 MB pure stream. FINAL (R2 form, measured
// best: 36.77us kernel / 45.09us wall, DRAM 74.2% = mixed-R/W HBM roofline).
//
// Design: one CTA per sequence position, 256 threads x float4 = one PE row.
// Each thread computes its 2 sin/cos pairs ONCE in registers (2x sincosf,
// amortized over the batch dim), then streams the 8 batch copies. Streaming
// ld/st hints, 2-deep load pipeline, 32-bit indexing.
//
// Levers tested and rejected (all neutral/negative at this roofline):
//  - L2 evict_last/evict_first policy pinning, full and partial (R3-R5)
//  - 256-bit v8.f32 LDG/STG (R6: -12%, fewer in-flight requests)
//  - persistent single-wave grid (R7: -25%, loses cross-wave rebalancing)

#define SEQ_LEN 4096
#define D_MODEL 1024
#define BATCH   8
#define THREADS 256   // 256 threads * float4 = 1024 floats = one PE row

__global__ void __launch_bounds__(THREADS, 8)
pe_add_kernel(const float4* __restrict__ in, float4* __restrict__ out) {
    const int pos = blockIdx.x;        // sequence position 0..4095
    const int t   = threadIdx.x;       // float4 index within row 0..255

    // PE for this thread's float4 (dims 4t..4t+3), computed once, reused 8x.
    const float LOG2_10000 = 13.287712379549449f;
    const float fpos = (float)pos;

    float e0 = (float)(4 * t)     * (1.0f / 1024.0f);
    float e1 = (float)(4 * t + 2) * (1.0f / 1024.0f);
    float a0 = fpos / exp2f(e0 * LOG2_10000);
    float a1 = fpos / exp2f(e1 * LOG2_10000);

    float s0, c0, s1, c1;
    sincosf(a0, &s0, &c0);   // accurate variant: angles reach ~4095 rad
    sincosf(a1, &s1, &c1);

    const float4 pe = make_float4(s0, c0, s1, c1);

    // 32-bit element offsets in float4 units.
    const int row_f4       = D_MODEL / 4;            // 256
    const int batch_stride = SEQ_LEN * row_f4;       // 1,048,576
    int idx = pos * row_f4 + t;

    // 2-deep pipeline: keep the next batch's load in flight while storing.
    float4 cur = __ldcs(in + idx);
#pragma unroll
    for (int b = 0; b < BATCH; ++b) {
        int next_idx = idx + batch_stride;
        float4 nxt;
        if (b < BATCH - 1) nxt = __ldcs(in + next_idx);
        float4 v = cur;
        v.x += pe.x;
        v.y += pe.y;
        v.z += pe.z;
        v.w += pe.w;
        __stcs(out + idx, v);
        cur = nxt;
        idx = next_idx;
    }
}

extern "C" void kernel_launch(void* const* d_in, const int* in_sizes, int n_in,
                              void* d_out, int out_size) {
    const float4* in  = (const float4*)d_in[0];
    float4*       out = (float4*)d_out;
    pe_add_kernel<<<SEQ_LEN, THREADS>>>(in, out);
}

// round 9
// speedup vs baseline: 1.2022x; 1.0188x over previous
#include <cuda_runtime.h>

// out[b, s, d] = in[b, s, d] + PE[s, d]
// PE[s, 2i]   = sin(s / 10000^(2i/1024)),  PE[s, 2i+1] = cos(...)
//
// B=8, S=4096, D=1024, fp32 — 268 MB pure stream, DRAM-bound (~73% spec).
// R9: halve CTA granularity. Grid (4096 pos, 2 batch-halves), each CTA
// streams 4 batches instead of 8 -> 8192 shorter CTAs. Halves the ragged
// final-wave drain quantum and gives the CTA scheduler 2x rebalancing
// opportunities (R7 showed oversubscription+work-stealing is the winning
// regime). sincos cost doubles (computed per CTA) but stays ~10us of MUFU
// spread across a 37us memory shadow — hidden.
// Prior rejected levers: L2 policy pinning (R3-5), 256-bit ops (R6),
// persistent single wave (R7).

#define SEQ_LEN 4096
#define D_MODEL 1024
#define BATCH   8
#define BSPLIT  2                      // batch halves per position
#define BPER    (BATCH / BSPLIT)       // 4 batches per CTA
#define THREADS 256                    // 256 x float4 = one PE row

__global__ void __launch_bounds__(THREADS, 8)
pe_add_kernel(const float4* __restrict__ in, float4* __restrict__ out) {
    const int pos   = blockIdx.x;      // sequence position 0..4095
    const int bhalf = blockIdx.y;      // batch half 0..1
    const int t     = threadIdx.x;     // float4 index within row 0..255

    // PE for this thread's float4 (dims 4t..4t+3), computed once, reused 4x.
    const float LOG2_10000 = 13.287712379549449f;
    const float fpos = (float)pos;

    float e0 = (float)(4 * t)     * (1.0f / 1024.0f);
    float e1 = (float)(4 * t + 2) * (1.0f / 1024.0f);
    float a0 = fpos / exp2f(e0 * LOG2_10000);
    float a1 = fpos / exp2f(e1 * LOG2_10000);

    float s0, c0, s1, c1;
    sincosf(a0, &s0, &c0);   // accurate variant: angles reach ~4095 rad
    sincosf(a1, &s1, &c1);

    const float4 pe = make_float4(s0, c0, s1, c1);

    // 32-bit element offsets in float4 units.
    const int row_f4       = D_MODEL / 4;            // 256
    const int batch_stride = SEQ_LEN * row_f4;       // 1,048,576
    int idx = (bhalf * BPER) * batch_stride + pos * row_f4 + t;

    // 2-deep pipeline over this CTA's 4 batches.
    float4 cur = __ldcs(in + idx);
#pragma unroll
    for (int b = 0; b < BPER; ++b) {
        int next_idx = idx + batch_stride;
        float4 nxt;
        if (b < BPER - 1) nxt = __ldcs(in + next_idx);
        float4 v = cur;
        v.x += pe.x;
        v.y += pe.y;
        v.z += pe.z;
        v.w += pe.w;
        __stcs(out + idx, v);
        cur = nxt;
        idx = next_idx;
    }
}

extern "C" void kernel_launch(void* const* d_in, const int* in_sizes, int n_in,
                              void* d_out, int out_size) {
    const float4* in  = (const float4*)d_in[0];
    float4*       out = (float4*)d_out;
    dim3 grid(SEQ_LEN, BSPLIT);
    pe_add_kernel<<<grid, THREADS>>>(in, out);
}

// round 10
// speedup vs baseline: 1.2252x; 1.0191x over previous
#include <cuda_runtime.h>

// out[b, s, d] = in[b, s, d] + PE[s, d]
// PE[s, 2i]   = sin(s / 10000^(2i/1024)),  PE[s, 2i+1] = cos(...)
//
// B=8, S=4096, D=1024, fp32 — 268 MB pure stream, DRAM-bound.
// R10: continue the R9 granularity gradient. R9 (4 batches/CTA, 8192 CTAs)
// won: 37.4 -> 36.4us kernel, DRAM 72.8 -> 74.6%. Now 2 batches/CTA,
// 16384 CTAs: drain quantum halves again. sincos duplication doubles
// (fma ~11 -> ~18%) but stays hidden under the 36us memory shadow.
// Rejected levers: L2 policy pinning (R3-5), 256-bit ops (R6), persistent
// single wave (R7), 8-batch monolithic CTAs (R1-R8 plateau).

#define SEQ_LEN 4096
#define D_MODEL 1024
#define BATCH   8
#define BSPLIT  4                      // batch quarters per position
#define BPER    (BATCH / BSPLIT)       // 2 batches per CTA
#define THREADS 256                    // 256 x float4 = one PE row

__global__ void __launch_bounds__(THREADS, 8)
pe_add_kernel(const float4* __restrict__ in, float4* __restrict__ out) {
    const int pos  = blockIdx.x;       // sequence position 0..4095
    const int bseg = blockIdx.y;       // batch segment 0..3
    const int t    = threadIdx.x;      // float4 index within row 0..255

    // PE for this thread's float4 (dims 4t..4t+3), computed once, reused 2x.
    const float LOG2_10000 = 13.287712379549449f;
    const float fpos = (float)pos;

    float e0 = (float)(4 * t)     * (1.0f / 1024.0f);
    float e1 = (float)(4 * t + 2) * (1.0f / 1024.0f);
    float a0 = fpos / exp2f(e0 * LOG2_10000);
    float a1 = fpos / exp2f(e1 * LOG2_10000);

    float s0, c0, s1, c1;
    sincosf(a0, &s0, &c0);   // accurate variant: angles reach ~4095 rad
    sincosf(a1, &s1, &c1);

    const float4 pe = make_float4(s0, c0, s1, c1);

    // 32-bit element offsets in float4 units.
    const int row_f4       = D_MODEL / 4;            // 256
    const int batch_stride = SEQ_LEN * row_f4;       // 1,048,576
    int idx = (bseg * BPER) * batch_stride + pos * row_f4 + t;

    // 2-deep pipeline over this CTA's 2 batches.
    float4 cur = __ldcs(in + idx);
#pragma unroll
    for (int b = 0; b < BPER; ++b) {
        int next_idx = idx + batch_stride;
        float4 nxt;
        if (b < BPER - 1) nxt = __ldcs(in + next_idx);
        float4 v = cur;
        v.x += pe.x;
        v.y += pe.y;
        v.z += pe.z;
        v.w += pe.w;
        __stcs(out + idx, v);
        cur = nxt;
        idx = next_idx;
    }
}

extern "C" void kernel_launch(void* const* d_in, const int* in_sizes, int n_in,
                              void* d_out, int out_size) {
    const float4* in  = (const float4*)d_in[0];
    float4*       out = (float4*)d_out;
    dim3 grid(SEQ_LEN, BSPLIT);
    pe_add_kernel<<<grid, THREADS>>>(in, out);
}